// round 8
// baseline (speedup 1.0000x reference)
#include <cuda_runtime.h>
#include <cuda_bf16.h>
#include <math.h>

#define BATCH   4
#define SLEN    2048
#define DDIM    1024
#define OUTD    1024
#define MSUM    (BATCH * SLEN)          // 8192

// ---------------------------------------------------------------------------
// Device-global scratch (allocation-free rule). bf16 hi/lo plane pairs.
// ---------------------------------------------------------------------------
__device__ __align__(256) __nv_bfloat16 g_XH[MSUM * DDIM],  g_XL[MSUM * DDIM];
__device__ __align__(256) __nv_bfloat16 g_YH[MSUM * DDIM],  g_YL[MSUM * DDIM];
__device__ __align__(256) __nv_bfloat16 g_WTH[3 * OUTD * DDIM], g_WTL[3 * OUTD * DDIM]; // W^T planes
__device__ __align__(256) __nv_bfloat16 g_QH[MSUM * OUTD],  g_QL[MSUM * OUTD];
__device__ __align__(256) __nv_bfloat16 g_KH[MSUM * OUTD],  g_KL[MSUM * OUTD];
__device__ __align__(256) __nv_bfloat16 g_VTH[BATCH * OUTD * SLEN], g_VTL[BATCH * OUTD * SLEN]; // V^T
__device__ __align__(256) __nv_bfloat16 g_PH[BATCH * SLEN * SLEN],  g_PL[BATCH * SLEN * SLEN];  // probs
__device__ __align__(256) float g_Sc[BATCH * SLEN * SLEN];  // fp32 scores (64MB)

#define C_XH 1
#define C_XL 2
#define C_YH 3
#define C_YL 4
#define C_WTH 5
#define C_WTL 6
#define C_QH 7
#define C_QL 8
#define C_KH 9
#define C_KL 10
#define C_VTH 11
#define C_VTL 12
#define C_PH 13
#define C_PL 14

__device__ __forceinline__ __nv_bfloat16* bbuf(int code) {
    switch (code) {
        case C_XH: return g_XH;   case C_XL: return g_XL;
        case C_YH: return g_YH;   case C_YL: return g_YL;
        case C_WTH: return g_WTH; case C_WTL: return g_WTL;
        case C_QH: return g_QH;   case C_QL: return g_QL;
        case C_KH: return g_KH;   case C_KL: return g_KL;
        case C_VTH: return g_VTH; case C_VTL: return g_VTL;
        case C_PH: return g_PH;   case C_PL: return g_PL;
        default: return g_XH;
    }
}

// ---------------------------------------------------------------------------
// Baseline-ISA helpers (sm_80+): cp.async + ldmatrix + mma.sync
// ---------------------------------------------------------------------------
__device__ __forceinline__ unsigned smem_u32(const void* p) {
    unsigned a;
    asm("{ .reg .u64 t; cvta.to.shared.u64 t, %1; cvt.u32.u64 %0, t; }" : "=r"(a) : "l"(p));
    return a;
}
#define CP_ASYNC16(dst, src) \
    asm volatile("cp.async.cg.shared.global [%0], [%1], 16;" :: "r"(dst), "l"(src))
#define CP_COMMIT() asm volatile("cp.async.commit_group;")
#define CP_WAIT1()  asm volatile("cp.async.wait_group 1;")

#define LDSM4(r, addr) \
    asm volatile("ldmatrix.sync.aligned.m8n8.x4.shared.b16 {%0,%1,%2,%3}, [%4];" \
        : "=r"((r)[0]), "=r"((r)[1]), "=r"((r)[2]), "=r"((r)[3]) : "r"(addr))

#define MMA16816(d, a, b0, b1) \
    asm volatile("mma.sync.aligned.m16n8k16.row.col.f32.bf16.bf16.f32 " \
        "{%0,%1,%2,%3}, {%4,%5,%6,%7}, {%8,%9}, {%0,%1,%2,%3};" \
        : "+f"((d)[0]), "+f"((d)[1]), "+f"((d)[2]), "+f"((d)[3]) \
        : "r"((a)[0]), "r"((a)[1]), "r"((a)[2]), "r"((a)[3]), "r"(b0), "r"(b1))

// SMEM tile: rows of 32 bf16 = 64B = 4 chunks of 16B. Conflict-free swizzle:
// bank group of (row,c) = (row&1)*4 + (c ^ ((row>>1)&3)) -> all 8 lanes of an
// ldmatrix phase (8 consecutive rows, fixed c) hit distinct 16B groups.
__device__ __forceinline__ unsigned sw_off(int row, int chunk) {
    return (unsigned)(row * 64 + (((chunk ^ (row >> 1)) & 3) << 4));
}

// Stage: AH[128x32]@0 (8KB), AL@8192, BH[128x32]@16384, BL@24576. 32KB/stage.
#define STAGE_BYTES 32768
#define SMEM_DYN    (2 * STAGE_BYTES)

// One stage of cp.async: 2048 16B-chunks, 128 threads -> 16 each.
__device__ __forceinline__ void issue_stage(
    unsigned sb, int tid,
    const __nv_bfloat16* AH, const __nv_bfloat16* AL,
    const __nv_bfloat16* BH, const __nv_bfloat16* BL,
    long m0, long n0, long k0, int Kfull)
{
#pragma unroll
    for (int i = 0; i < 16; i++) {
        const int q = i * 128 + tid;          // 0..2047
        const int plane = q >> 9;             // 0=AH 1=AL 2=BH 3=BL
        const int aq = q & 511;
        const int row = aq >> 2, c = aq & 3;
        const __nv_bfloat16* src =
            (plane == 0) ? AH : (plane == 1) ? AL : (plane == 2) ? BH : BL;
        const long r0 = (plane < 2) ? m0 : n0;
        CP_ASYNC16(sb + (unsigned)(plane << 13) + sw_off(row, c),
                   src + (r0 + row) * (long)Kfull + k0 + c * 8);
    }
}

// ---------------------------------------------------------------------------
// Tensor-core GEMM: C[128x128 tile] = A[M,K] @ B[N,K]^T, hi/lo 3-term split.
// 128 threads = 4 warps (2m x 2n), warp tile 64x64, Kt=32, double-buffered.
// EPI: 0=bf16 hi/lo, 1=transposed hi/lo (V->V^T), 2=fp32*alpha (opt. g_Sc).
// ---------------------------------------------------------------------------
template<int EPI>
__global__ void __launch_bounds__(128)
mma_gemm(int ahc, int alc, long aoff, long sA,
         int bhc, int blc, long boff, long sB,
         int ohc, int olc, float* of32, int use_sc, long ooff, long sO, int ldo,
         int Kfull, float alpha)
{
    extern __shared__ __align__(16) char smem[];
    const unsigned sbase = smem_u32(smem);
    const int tid  = threadIdx.x;
    const int lane = tid & 31;
    const int wid  = tid >> 5;
    const int warp_m = wid >> 1;     // 0..1
    const int warp_n = wid & 1;      // 0..1
    const int z  = blockIdx.z;
    const long m0 = (long)blockIdx.y * 128;
    const long n0 = (long)blockIdx.x * 128;

    const __nv_bfloat16* AH = bbuf(ahc) + aoff + (long)z * sA;
    const __nv_bfloat16* AL = bbuf(alc) + aoff + (long)z * sA;
    const __nv_bfloat16* BH = bbuf(bhc) + boff + (long)z * sB;
    const __nv_bfloat16* BL = bbuf(blc) + boff + (long)z * sB;

    float acc[4][8][4];
#pragma unroll
    for (int mi = 0; mi < 4; mi++)
#pragma unroll
        for (int ni = 0; ni < 8; ni++)
#pragma unroll
            for (int r = 0; r < 4; r++) acc[mi][ni][r] = 0.0f;

    const int nk = Kfull >> 5;   // K-tiles of 32

    issue_stage(sbase,               tid, AH, AL, BH, BL, m0, n0, 0,  Kfull); CP_COMMIT();
    issue_stage(sbase + STAGE_BYTES, tid, AH, AL, BH, BL, m0, n0, 32, Kfull); CP_COMMIT();

    for (int c = 0; c < nk; c++) {
        CP_WAIT1();
        __syncthreads();
        const unsigned sb = sbase + (unsigned)((c & 1) * STAGE_BYTES);

#pragma unroll
        for (int kk2 = 0; kk2 < 2; kk2++) {          // k16 halves of the k32 tile
            const int ck = kk2 * 2;                  // 16B-chunk base (k/8)
            unsigned aH[2][4], aL[2][4], bH[4][4], bL[4][4];
            // A frags: m16 blocks (mi pair handled 2 at a time to bound regs? no:
            // 2 LDSM4 per plane cover m32; need m64 -> 4 blocks, load all)
            unsigned aH2[4][4], aL2[4][4];
#pragma unroll
            for (int mi = 0; mi < 4; mi++) {
                const int r = warp_m * 64 + mi * 16 + (lane & 15);
                const unsigned off = sw_off(r, ck + (lane >> 4));
                LDSM4(aH2[mi], sb + off);
                LDSM4(aL2[mi], sb + 8192u + off);
            }
            // B frags: 4 groups of n16 cover n64; x4 gives {n0-7 k0-7, n8-15 k0-7,
            // n0-7 k8-15, n8-15 k8-15} -> ni even uses regs {0,2}, odd {1,3}
#pragma unroll
            for (int g = 0; g < 4; g++) {
                const int rn = warp_n * 64 + g * 16 + (lane & 15);
                const unsigned off = sw_off(rn, ck + (lane >> 4));
                LDSM4(bH[g], sb + 16384u + off);
                LDSM4(bL[g], sb + 24576u + off);
            }
#pragma unroll
            for (int mi = 0; mi < 4; mi++)
#pragma unroll
                for (int ni = 0; ni < 8; ni++) {
                    const int g = ni >> 1, o = ni & 1;
                    MMA16816(acc[mi][ni], aH2[mi], bH[g][o], bH[g][o + 2]);
                    MMA16816(acc[mi][ni], aH2[mi], bL[g][o], bL[g][o + 2]);
                    MMA16816(acc[mi][ni], aL2[mi], bH[g][o], bH[g][o + 2]);
                }
            (void)aH; (void)aL;
        }
        __syncthreads();
        if (c + 2 < nk)
            issue_stage(sbase + (unsigned)((c & 1) * STAGE_BYTES), tid,
                        AH, AL, BH, BL, m0, n0, (long)(c + 2) * 32, Kfull);
        CP_COMMIT();   // uniform group accounting
    }

    // ---- epilogue ----
#pragma unroll
    for (int mi = 0; mi < 4; mi++)
#pragma unroll
        for (int ni = 0; ni < 8; ni++)
#pragma unroll
            for (int r = 0; r < 4; r++) {
                const int row = warp_m * 64 + mi * 16 + (lane >> 2) + ((r & 2) ? 8 : 0);
                const int col = warp_n * 64 + ni * 8 + ((lane & 3) << 1) + (r & 1);
                const float v = acc[mi][ni][r];
                const long gm = m0 + row;
                if (EPI == 2) {
                    float* O = (use_sc ? g_Sc : of32);
                    O[ooff + (long)z * sO + gm * (long)ldo + n0 + col] = v * alpha;
                } else if (EPI == 0) {
                    __nv_bfloat16* OH = bbuf(ohc);
                    __nv_bfloat16* OL = bbuf(olc);
                    const long a = ooff + (long)z * sO + gm * (long)ldo + n0 + col;
                    const __nv_bfloat16 h = __float2bfloat16(v);
                    OH[a] = h;
                    OL[a] = __float2bfloat16(v - __bfloat162float(h));
                } else {   // EPI == 1: V -> V^T[b][o][s]
                    __nv_bfloat16* OH = bbuf(ohc);
                    __nv_bfloat16* OL = bbuf(olc);
                    const long b = gm >> 11;
                    const long s = gm & (SLEN - 1);
                    const long a = b * (long)OUTD * SLEN + (n0 + col) * (long)SLEN + s;
                    const __nv_bfloat16 h = __float2bfloat16(v);
                    OH[a] = h;
                    OL[a] = __float2bfloat16(v - __bfloat162float(h));
                }
            }
}

// ---------------------------------------------------------------------------
// fp32 -> bf16 hi/lo planes (elementwise)
// ---------------------------------------------------------------------------
__global__ void cvt_hilo(const float* __restrict__ src, int hic, int loc, long n)
{
    __nv_bfloat16* H = bbuf(hic);
    __nv_bfloat16* L = bbuf(loc);
    for (long i = (long)blockIdx.x * blockDim.x + threadIdx.x; i < n;
         i += (long)gridDim.x * blockDim.x) {
        const float v = src[i];
        const __nv_bfloat16 h = __float2bfloat16(v);
        H[i] = h;
        L[i] = __float2bfloat16(v - __bfloat162float(h));
    }
}

// ---------------------------------------------------------------------------
// W[3][K=d][N=o] -> WT[3][o][d] hi/lo planes (tiled transpose)
// ---------------------------------------------------------------------------
__global__ void cvt_w_t(const float* __restrict__ W)
{
    __shared__ float tile[32][33];
    const int z = blockIdx.z;
    const int k0 = blockIdx.x * 32;
    const int n0 = blockIdx.y * 32;
    const int tx = threadIdx.x, ty = threadIdx.y;  // (32, 8)
    const long base = (long)z * DDIM * OUTD;
#pragma unroll
    for (int i = 0; i < 32; i += 8)
        tile[ty + i][tx] = W[base + (long)(k0 + ty + i) * OUTD + n0 + tx];
    __syncthreads();
#pragma unroll
    for (int i = 0; i < 32; i += 8) {
        const float v = tile[tx][ty + i];
        const __nv_bfloat16 h = __float2bfloat16(v);
        const long a = base + (long)(n0 + ty + i) * DDIM + k0 + tx;
        g_WTH[a] = h;
        g_WTL[a] = __float2bfloat16(v - __bfloat162float(h));
    }
}

// ---------------------------------------------------------------------------
// Row softmax over fp32 scores -> bf16 hi/lo prob planes
// ---------------------------------------------------------------------------
__global__ void __launch_bounds__(256, 4)
softmax_cvt()
{
    const long base = (long)blockIdx.x * SLEN;
    const int tid = threadIdx.x;
    __shared__ float red[8];

    float lmax = -3.0e38f;
    for (int i = tid; i < SLEN; i += 256)
        lmax = fmaxf(lmax, g_Sc[base + i]);
#pragma unroll
    for (int o = 16; o > 0; o >>= 1)
        lmax = fmaxf(lmax, __shfl_xor_sync(0xFFFFFFFFu, lmax, o));
    if ((tid & 31) == 0) red[tid >> 5] = lmax;
    __syncthreads();
    float rmax = red[0];
#pragma unroll
    for (int w = 1; w < 8; w++) rmax = fmaxf(rmax, red[w]);
    __syncthreads();

    float lsum = 0.0f;
    for (int i = tid; i < SLEN; i += 256) {
        const float e = __expf(g_Sc[base + i] - rmax);
        g_Sc[base + i] = e;
        lsum += e;
    }
#pragma unroll
    for (int o = 16; o > 0; o >>= 1)
        lsum += __shfl_xor_sync(0xFFFFFFFFu, lsum, o);
    if ((tid & 31) == 0) red[tid >> 5] = lsum;
    __syncthreads();
    float rsum = 0.0f;
#pragma unroll
    for (int w = 0; w < 8; w++) rsum += red[w];

    const float inv = 1.0f / rsum;
    for (int i = tid; i < SLEN; i += 256) {
        const float p = g_Sc[base + i] * inv;
        const __nv_bfloat16 h = __float2bfloat16(p);
        g_PH[base + i] = h;
        g_PL[base + i] = __float2bfloat16(p - __bfloat162float(h));
    }
}

// ---------------------------------------------------------------------------
// Launch
// ---------------------------------------------------------------------------
extern "C" void kernel_launch(void* const* d_in, const int* in_sizes, int n_in,
                              void* d_out, int out_size)
{
    const float* x = (const float*)d_in[0];   // [4,2048,1024]
    const float* y = (const float*)d_in[1];   // [4,2048,1024]
    const float* w = (const float*)d_in[2];   // [3,1024,1024]
    float* out = (float*)d_out;               // [4,2048,1024]

    // Allow 64KB dynamic smem (host-side attribute set; capture-safe, idempotent)
    cudaFuncSetAttribute((const void*)mma_gemm<0>, cudaFuncAttributeMaxDynamicSharedMemorySize, SMEM_DYN);
    cudaFuncSetAttribute((const void*)mma_gemm<1>, cudaFuncAttributeMaxDynamicSharedMemorySize, SMEM_DYN);
    cudaFuncSetAttribute((const void*)mma_gemm<2>, cudaFuncAttributeMaxDynamicSharedMemorySize, SMEM_DYN);

    // fp32 -> bf16 hi/lo conversions
    cvt_hilo<<<1024, 256>>>(x, C_XH, C_XL, (long)MSUM * DDIM);
    cvt_hilo<<<1024, 256>>>(y, C_YH, C_YL, (long)MSUM * DDIM);
    cvt_w_t<<<dim3(DDIM / 32, OUTD / 32, 3), dim3(32, 8)>>>(w);

    const long WSL = (long)OUTD * DDIM;  // 1M per weight slice
    dim3 blk(128);

    // Projections: [8192,1024] @ W^T slice, CTA tile 128x128
    dim3 gproj(OUTD / 128, MSUM / 128, 1);     // (8, 64)
    mma_gemm<0><<<gproj, blk, SMEM_DYN>>>(C_XH, C_XL, 0, 0,
                                          C_WTH, C_WTL, 0 * WSL, 0,
                                          C_QH, C_QL, nullptr, 0, 0, 0, OUTD, DDIM, 1.0f);
    mma_gemm<0><<<gproj, blk, SMEM_DYN>>>(C_XH, C_XL, 0, 0,
                                          C_WTH, C_WTL, 1 * WSL, 0,
                                          C_KH, C_KL, nullptr, 0, 0, 0, OUTD, DDIM, 1.0f);
    mma_gemm<1><<<gproj, blk, SMEM_DYN>>>(C_YH, C_YL, 0, 0,
                                          C_WTH, C_WTL, 2 * WSL, 0,
                                          C_VTH, C_VTL, nullptr, 0, 0, 0, 0, DDIM, 1.0f);

    // Scores: per batch Q @ K^T * (1/32) -> fp32 g_Sc
    dim3 gsc(SLEN / 128, SLEN / 128, BATCH);   // (16, 16, 4)
    mma_gemm<2><<<gsc, blk, SMEM_DYN>>>(C_QH, C_QL, 0, (long)SLEN * OUTD,
                                        C_KH, C_KL, 0, (long)SLEN * OUTD,
                                        0, 0, nullptr, 1, 0, (long)SLEN * SLEN, SLEN,
                                        OUTD, 0.03125f);

    // Softmax + prob hi/lo planes
    softmax_cvt<<<BATCH * SLEN, 256>>>();

    // AV: per batch P @ (V^T)^T -> out fp32
    dim3 gav(OUTD / 128, SLEN / 128, BATCH);   // (8, 16, 4)
    mma_gemm<2><<<gav, blk, SMEM_DYN>>>(C_PH, C_PL, 0, (long)SLEN * SLEN,
                                        C_VTH, C_VTL, 0, (long)OUTD * SLEN,
                                        0, 0, out, 0, 0, (long)SLEN * OUTD, OUTD,
                                        SLEN, 1.0f);
}